// round 12
// baseline (speedup 1.0000x reference)
#include <cuda_runtime.h>
#include <cstdint>

// DenseRoutingMaskLayer: per-row argmax over 8 routing logits selects a
// contiguous 512-float chunk of the 4096-wide input row.
//   inputs:          [B=16384, D=4096] f32   (d_in[0])
//   routing_inputs:  [B=16384, R=8]    f32   (d_in[1])
//   out:             [B=16384, W=512]  f32
//
// Round 12: single-wave grid (1024 CTAs < 148 SMs x 8 CTAs resident) with
// 2 rows per warp processed SEQUENTIALLY (no double-buffering -> regs stay
// ~26, occupancy ~70%, unlike R4's 46-reg buffered variant).
//  - both argmaxes computed up front from ONE coalesced 16-lane routing
//    load + 8-lane butterfly + ballot/ffs (first-occurrence ties).
//  - copy per row: 4x __ldcg batched, then 4x __stcs (R8's winning hints:
//    reads L2-cached, writes evict-first).

constexpr int WARPS_PER_CTA = 8;
constexpr int ROWS_PER_CTA  = 16;   // 2 rows per warp

__global__ __launch_bounds__(256, 8)
void dense_routing_mask_kernel(const float* __restrict__ inputs,
                               const float* __restrict__ routing,
                               float* __restrict__ out) {
    const int warp = threadIdx.x >> 5;
    const int lane = threadIdx.x & 31;
    const int row0 = blockIdx.x * ROWS_PER_CTA + warp * 2;

    // ---- routing: 2 rows x 8 logits in one coalesced load (lanes 0-15) ----
    const float NEG_INF = -__int_as_float(0x7f800000);
    float v = (lane < 16) ? __ldg(routing + row0 * 8 + lane) : NEG_INF;

    float m = v;
    #pragma unroll
    for (int off = 1; off < 8; off <<= 1)
        m = fmaxf(m, __shfl_xor_sync(0xffffffffu, m, off));

    const unsigned bal = __ballot_sync(0xffffffffu, v == m);
    const int idx0 = __ffs(bal & 0xFFu) - 1;          // row0   (first occ.)
    const int idx1 = __ffs((bal >> 8) & 0xFFu) - 1;   // row0+1 (first occ.)

    // ---- row 0: load 4, store 4 ----
    {
        const float4* __restrict__ src = reinterpret_cast<const float4*>(inputs)
            + row0 * 1024 + idx0 * 128;
        float4* __restrict__ dst = reinterpret_cast<float4*>(out) + row0 * 128;

        float4 t0 = __ldcg(src + lane);
        float4 t1 = __ldcg(src + lane + 32);
        float4 t2 = __ldcg(src + lane + 64);
        float4 t3 = __ldcg(src + lane + 96);
        __stcs(dst + lane,      t0);
        __stcs(dst + lane + 32, t1);
        __stcs(dst + lane + 64, t2);
        __stcs(dst + lane + 96, t3);
    }

    // ---- row 1: load 4, store 4 ----
    {
        const int row1 = row0 + 1;
        const float4* __restrict__ src = reinterpret_cast<const float4*>(inputs)
            + row1 * 1024 + idx1 * 128;
        float4* __restrict__ dst = reinterpret_cast<float4*>(out) + row1 * 128;

        float4 t0 = __ldcg(src + lane);
        float4 t1 = __ldcg(src + lane + 32);
        float4 t2 = __ldcg(src + lane + 64);
        float4 t3 = __ldcg(src + lane + 96);
        __stcs(dst + lane,      t0);
        __stcs(dst + lane + 32, t1);
        __stcs(dst + lane + 64, t2);
        __stcs(dst + lane + 96, t3);
    }
}

extern "C" void kernel_launch(void* const* d_in, const int* in_sizes, int n_in,
                              void* d_out, int out_size) {
    const float* inputs  = (const float*)d_in[0];
    const float* routing = (const float*)d_in[1];
    float* out = (float*)d_out;

    const int B = in_sizes[1] / 8;               // 16384
    const int blocks = B / ROWS_PER_CTA;         // 1024 -> single resident wave

    dense_routing_mask_kernel<<<blocks, 256>>>(inputs, routing, out);
}

// round 13
// speedup vs baseline: 1.0088x; 1.0088x over previous
#include <cuda_runtime.h>
#include <cstdint>

// DenseRoutingMaskLayer: per-row argmax over 8 routing logits selects a
// contiguous 512-float chunk of the 4096-wide input row.
//   inputs:          [B=16384, D=4096] f32   (d_in[0])
//   routing_inputs:  [B=16384, R=8]    f32   (d_in[1])
//   out:             [B=16384, W=512]  f32
//
// FINAL (R8 form, best measured: 10.40us = ~6.2 TB/s combined traffic,
// at the DRAM service-rate roofline for the 64.5MB mandatory footprint).
//  - 1 row per warp, 8 warps/CTA, grid 2048; regs 24, occ ~70%.
//  - argmax via two uniform float4 broadcast loads + branchless depth-3
//    comparison tree; strict '>' keeps the lower index, matching
//    jnp.argmax first-occurrence tie-break.
//  - chunk copy: 4x __ldcg (L2-cached reads) batched before 4x __stcs
//    (evict-first writes: the only lever that measurably helped, -2.4%).
// Measured-worse alternatives: higher occupancy (R5), register-buffered
// multi-row MLP (R2/R4), TMA bulk (R3), 256-bit LDG/STG (R11),
// evict-last reads (R10), single-wave sequential rows (R12).

struct VI { float v; int i; };

__device__ __forceinline__ VI vmax(VI a, VI b) {
    // b has the higher index; keep a on ties -> first occurrence wins
    VI r;
    r.v = (b.v > a.v) ? b.v : a.v;
    r.i = (b.v > a.v) ? b.i : a.i;
    return r;
}

__global__ __launch_bounds__(256, 8)
void dense_routing_mask_kernel(const float* __restrict__ inputs,
                               const float* __restrict__ routing,
                               float* __restrict__ out) {
    const int warp = threadIdx.x >> 5;
    const int lane = threadIdx.x & 31;
    const int row  = blockIdx.x * 8 + warp;

    // ---- argmax: all lanes load the same 8 logits (broadcast) ----
    const float4* r4 = reinterpret_cast<const float4*>(routing) + row * 2;
    const float4 a = __ldg(r4);
    const float4 b = __ldg(r4 + 1);

    VI m01 = vmax(VI{a.x, 0}, VI{a.y, 1});
    VI m23 = vmax(VI{a.z, 2}, VI{a.w, 3});
    VI m45 = vmax(VI{b.x, 4}, VI{b.y, 5});
    VI m67 = vmax(VI{b.z, 6}, VI{b.w, 7});
    VI m03 = vmax(m01, m23);
    VI m47 = vmax(m45, m67);
    const int idx = vmax(m03, m47).i;

    // ---- copy the selected 512-float chunk: 128 float4, 4 per lane ----
    const float4* __restrict__ src = reinterpret_cast<const float4*>(inputs)
        + row * 1024 + idx * 128;
    float4* __restrict__ dst = reinterpret_cast<float4*>(out) + row * 128;

    float4 t0 = __ldcg(src + lane);
    float4 t1 = __ldcg(src + lane + 32);
    float4 t2 = __ldcg(src + lane + 64);
    float4 t3 = __ldcg(src + lane + 96);

    __stcs(dst + lane,      t0);
    __stcs(dst + lane + 32, t1);
    __stcs(dst + lane + 64, t2);
    __stcs(dst + lane + 96, t3);
}

extern "C" void kernel_launch(void* const* d_in, const int* in_sizes, int n_in,
                              void* d_out, int out_size) {
    const float* inputs  = (const float*)d_in[0];
    const float* routing = (const float*)d_in[1];
    float* out = (float*)d_out;

    const int B = in_sizes[1] / 8;   // 16384
    const int blocks = B / 8;        // 2048 (8 warps per CTA, 1 row per warp)

    dense_routing_mask_kernel<<<blocks, 256>>>(inputs, routing, out);
}